// round 13
// baseline (speedup 1.0000x reference)
#include <cuda_runtime.h>
#include <cuda_fp16.h>
#include <math.h>
#include <stdint.h>

#define Dm 1024
#define Fm 4096
#define Em 8
#define Tm 4096
#define TK (Tm*2)

// ---------------- scratch (static device globals) ----------------
__device__ int    g_count[Em];
__device__ int    g_entries[Em*Tm];      // per-expert list: token index
__device__ int    g_slot[TK];            // token,k -> e*Tm+pos
__device__ float  g_topw[TK];
__device__ __half g_Xh[(size_t)Tm*Dm];           // fp16, k-permuted (32-blocks)
__device__ __half g_W1h[(size_t)Em*Fm*Dm];       // fp16, k-permuted
__device__ __half g_W2h[(size_t)Em*Dm*Fm];       // fp16, k-permuted
__device__ __half g_H[(size_t)Em*Tm*Fm];         // [e][pos][F] fp16 k-permuted
__device__ float  g_Y[(size_t)Em*Tm*Dm];         // [e][pos][D] fp32

// k-permutation within each 32-element block: thread qc's fragments for the
// two k16-steps are 16 contiguous bytes: offset = qc*8 + s*4 + v.
__device__ __forceinline__ int kperm32(int kk) {
    int qc = (kk & 7) >> 1;
    int s  = (kk >> 4) & 1;
    int v  = (kk & 1) | ((kk & 8) >> 2);
    return (qc << 3) + (s << 2) + v;
}

// ---------------- PTX helpers (base sm_90 ISA only) ----------------
__device__ __forceinline__ uint32_t s2u(const void* p) {
    uint32_t a;
    asm("{ .reg .u64 t; cvta.to.shared.u64 t, %1; cvt.u32.u64 %0, t; }" : "=r"(a) : "l"(p));
    return a;
}

__device__ __forceinline__ void mma_f16(float* d,
                                        uint32_t a0, uint32_t a1, uint32_t a2, uint32_t a3,
                                        uint32_t b0, uint32_t b1) {
    asm volatile(
        "mma.sync.aligned.m16n8k16.row.col.f32.f16.f16.f32 "
        "{%0,%1,%2,%3}, {%4,%5,%6,%7}, {%8,%9}, {%0,%1,%2,%3};"
        : "+f"(d[0]), "+f"(d[1]), "+f"(d[2]), "+f"(d[3])
        : "r"(a0), "r"(a1), "r"(a2), "r"(a3), "r"(b0), "r"(b1));
}

#define BULK64(dst, src, mbar) \
    asm volatile("cp.async.bulk.shared::cluster.global.mbarrier::complete_tx::bytes [%0], [%1], %2, [%3];" \
        :: "r"(dst), "l"(src), "r"(64), "r"(mbar) : "memory")

#define MBAR_INIT(mbar, cnt) \
    asm volatile("mbarrier.init.shared.b64 [%0], %1;" :: "r"(mbar), "r"((uint32_t)(cnt)) : "memory")
#define MBAR_EXPECT_TX(mbar, bytes) \
    asm volatile("mbarrier.arrive.expect_tx.shared.b64 _, [%0], %1;" :: "r"(mbar), "r"((uint32_t)(bytes)) : "memory")

#define WAIT_PARITY(mbar, ph) do {                                               \
    uint32_t _m = (mbar), _p = (uint32_t)(ph), _d;                               \
    asm volatile(                                                                \
        "{\n\t.reg .pred p;\n\t"                                                 \
        "mbarrier.try_wait.parity.acquire.cta.shared::cta.b64 p, [%1], %2;\n\t"  \
        "selp.b32 %0, 1, 0, p;\n\t}"                                             \
        : "=r"(_d) : "r"(_m), "r"(_p) : "memory");                               \
    if (!_d) {                                                                   \
        asm volatile(                                                            \
            "{\n\t.reg .pred P1;\n\t"                                            \
            "W_%=:\n\t"                                                          \
            "mbarrier.try_wait.parity.acquire.cta.shared::cta.b64 P1, [%0], %1, 0x989680;\n\t" \
            "@P1 bra.uni D_%=;\n\t"                                              \
            "bra.uni W_%=;\n\t"                                                  \
            "D_%=:\n\t}"                                                         \
            :: "r"(_m), "r"(_p) : "memory");                                     \
    }                                                                            \
} while (0)

// ---------------- weight convert (both weights, one launch) ---------------
__global__ void convw_kernel(const float* __restrict__ W1, const float* __restrict__ W2,
                             __half* __restrict__ D1, __half* __restrict__ D2,
                             size_t n4) {
    size_t i4 = (size_t)blockIdx.x * blockDim.x + threadIdx.x;
    const float* src;
    __half* dst;
    size_t base;
    if (i4 < n4) { src = W1; dst = D1; base = i4 * 4; }
    else         { src = W2; dst = D2; base = (i4 - n4) * 4; }
    float4 v = *(const float4*)(src + base);
    int kk = (int)(base & 31);                  // 4-aligned
    int s    = (kk >> 4) & 1;
    int h_lo = ((kk & 7) >> 1) * 8 + s * 4 + ((kk & 8) >> 2);
    size_t out = base & ~(size_t)31;
    *(__half2*)(dst + out + h_lo)     = __floats2half2_rn(v.x, v.y);
    *(__half2*)(dst + out + h_lo + 8) = __floats2half2_rn(v.z, v.w);
}

// ---------------- router ----------------
__global__ void zero_counts_kernel() {
    if (threadIdx.x < Em) g_count[threadIdx.x] = 0;
}

__global__ void router_kernel(const float* __restrict__ x,
                              const float* __restrict__ Wr) {
    int w    = (blockIdx.x * blockDim.x + threadIdx.x) >> 5;
    int lane = threadIdx.x & 31;
    if (w >= Tm) return;
    const float* xr = x + (size_t)w * Dm;
    __half* xo = g_Xh + (size_t)w * Dm;
    float acc[Em];
#pragma unroll
    for (int e = 0; e < Em; e++) acc[e] = 0.f;
    for (int j = lane; j < Dm; j += 32) {
        float xv = xr[j];
        xo[(j & ~31) + kperm32(j & 31)] = __float2half_rn(xv);
#pragma unroll
        for (int e = 0; e < Em; e++) acc[e] = fmaf(xv, Wr[e*Dm + j], acc[e]);
    }
#pragma unroll
    for (int e = 0; e < Em; e++) {
#pragma unroll
        for (int off = 16; off; off >>= 1)
            acc[e] += __shfl_xor_sync(0xffffffffu, acc[e], off);
    }
    if (lane == 0) {
        int e0 = 0; float v0 = acc[0];
#pragma unroll
        for (int e = 1; e < Em; e++) if (acc[e] > v0) { v0 = acc[e]; e0 = e; }
        int e1 = -1; float v1 = -1e30f;
#pragma unroll
        for (int e = 0; e < Em; e++) if (e != e0 && acc[e] > v1) { v1 = acc[e]; e1 = e; }
        float b  = expf(v1 - v0);
        g_topw[w*2 + 0] = 1.f / (1.f + b);
        g_topw[w*2 + 1] = b  / (1.f + b);
        int p0 = atomicAdd(&g_count[e0], 1);
        g_entries[e0*Tm + p0] = w;
        g_slot[w*2 + 0] = e0*Tm + p0;
        int p1 = atomicAdd(&g_count[e1], 1);
        g_entries[e1*Tm + p1] = w;
        g_slot[w*2 + 1] = e1*Tm + p1;
    }
}

// ---------------- fp16 m16n8k16 GEMM, 3-deep pipeline, padding-free -------
// block tile 128(M) x 128(N), logical K-chunk 64 split into two 64B-row
// sub-buffers (16KB each). Zero padding: granule stride 4 -> LDS bank = lane.
// 8 warps @ 64x32. 3 logical stages x 32KB = 96KB -> 2 CTAs/SM.
#define SUB_BYTES 16384
#define LSTG_BYTES 32768
#define NSTG 3
#define SMEM_DYN (NSTG*LSTG_BYTES)                  // 98304
#define TX_BYTES 32768

template<int KTOT, int ASTRIDE, bool GATHER, int BSTRIDE, int NTOT, bool GELU>
__global__ __launch_bounds__(256, 2)
void moe_gemm(const __half* __restrict__ W,
              const float* __restrict__ bias)
{
    int e    = blockIdx.z;
    int cnt  = g_count[e];
    int row0 = blockIdx.y * 128;
    if (row0 >= cnt) return;
    int col0 = blockIdx.x * 128;

    extern __shared__ __align__(16) char dsm[];
    __shared__ __align__(8) uint64_t sMbar[NSTG];

    int tid  = threadIdx.x;
    int lane = tid & 31;
    int w    = tid >> 5;

    uint32_t sbase = s2u(dsm);
    uint32_t mb[NSTG];
#pragma unroll
    for (int s = 0; s < NSTG; s++) mb[s] = s2u(&sMbar[s]);

    if (tid == 0) {
#pragma unroll
        for (int s = 0; s < NSTG; s++) MBAR_INIT(mb[s], 1);
    }
    __syncthreads();

    // per-thread bulk source row: tid<128 -> A row tid; else B row tid-128
    const __half* src;
    uint32_t dst;      // offset of this thread's 64B row within sub-buffer 0
    if (tid < 128) {
        if (GATHER) {
            int i   = row0 + tid;
            int tok = g_entries[e*Tm + ((i < cnt) ? i : 0)];
            src = g_Xh + (size_t)tok*ASTRIDE;
        } else {
            src = g_H + (size_t)(e*Tm + row0 + tid)*ASTRIDE;
        }
        dst = sbase + tid*64;
    } else {
        src = W + (size_t)e*Fm*Dm + (size_t)(col0 + tid - 128)*BSTRIDE;
        dst = sbase + 8192 + (tid - 128)*64;
    }

    constexpr int NCHL = KTOT / 64;     // logical chunks

    auto loadChunk = [&](int l, int lstg) {
        if (tid == 0) MBAR_EXPECT_TX(mb[lstg], TX_BYTES);
        const char* s8 = (const char*)src + (size_t)l*128;
        uint32_t d = dst + lstg*LSTG_BYTES;
        BULK64(d,             s8,      mb[lstg]);   // k[0:32)  -> sub0
        BULK64(d + SUB_BYTES, s8 + 64, mb[lstg]);   // k[32:64) -> sub1
    };

    loadChunk(0, 0); loadChunk(1, 1); loadChunk(2, 2);

    float acc[4][4][4];
#pragma unroll
    for (int i = 0; i < 4; i++)
#pragma unroll
        for (int j = 0; j < 4; j++)
#pragma unroll
            for (int q = 0; q < 4; q++) acc[i][j][q] = 0.f;

    int wm = w & 1, wn = w >> 1;    // warp tile rows wm*64..+63, cols wn*32..+31
    int qr = lane >> 2;
    int qc = lane & 3;

    int lstg = 0, par = 0;

    for (int l = 0; l < NCHL; l++) {
        // distributed wait: warps start fragment loads as soon as TMA lands
        WAIT_PARITY(mb[lstg], par);

        const char* Lb = dsm + lstg*LSTG_BYTES;

#pragma unroll
        for (int sub = 0; sub < 2; sub++) {
            const char* As = Lb + sub*SUB_BYTES;
            const char* Bs = As + 8192;
            int ofs = qc*16;
            uint4 Alo[4], Ahi[4], Bv[4];
#pragma unroll
            for (int mt = 0; mt < 4; mt++) {
                int r = wm*64 + mt*16 + qr;
                Alo[mt] = *(const uint4*)(As + r*64 + ofs);
                Ahi[mt] = *(const uint4*)(As + (r+8)*64 + ofs);
            }
#pragma unroll
            for (int nt = 0; nt < 4; nt++) {
                int n = wn*32 + nt*8 + qr;
                Bv[nt] = *(const uint4*)(Bs + n*64 + ofs);
            }
#pragma unroll
            for (int s = 0; s < 2; s++) {
#pragma unroll
                for (int mt = 0; mt < 4; mt++) {
                    const uint32_t* al = (const uint32_t*)&Alo[mt];
                    const uint32_t* ah = (const uint32_t*)&Ahi[mt];
#pragma unroll
                    for (int nt = 0; nt < 4; nt++) {
                        const uint32_t* bb = (const uint32_t*)&Bv[nt];
                        mma_f16(acc[mt][nt],
                                al[2*s], ah[2*s], al[2*s+1], ah[2*s+1],
                                bb[2*s], bb[2*s+1]);
                    }
                }
            }
        }
        __syncthreads();                 // stage consumed by all warps
        if (l + NSTG < NCHL) loadChunk(l + NSTG, lstg);
        lstg++; if (lstg == NSTG) { lstg = 0; par ^= 1; }
    }

    // ---- epilogue ----
    const float* bia = bias + e*NTOT + col0;
#pragma unroll
    for (int mt = 0; mt < 4; mt++) {
        int r0 = wm*64 + mt*16 + qr;
#pragma unroll
        for (int nt = 0; nt < 4; nt++) {
            int cc = wn*32 + nt*8 + 2*qc;
            float bv0 = bia[cc], bv1 = bia[cc + 1];
            float t0 = acc[mt][nt][0] + bv0;
            float t1 = acc[mt][nt][1] + bv1;
            float t2 = acc[mt][nt][2] + bv0;
            float t3 = acc[mt][nt][3] + bv1;
            if (GELU) {
                t0 = 0.5f*t0*(1.f + erff(t0*0.70710678118654752f));
                t1 = 0.5f*t1*(1.f + erff(t1*0.70710678118654752f));
                t2 = 0.5f*t2*(1.f + erff(t2*0.70710678118654752f));
                t3 = 0.5f*t3*(1.f + erff(t3*0.70710678118654752f));
                int po = (cc & ~31) + kperm32(cc & 31);     // cc even -> v pair
                __half* h0 = g_H + (size_t)(e*Tm + row0 + r0)*NTOT + col0 + po;
                __half* h1 = g_H + (size_t)(e*Tm + row0 + r0 + 8)*NTOT + col0 + po;
                *(__half2*)h0 = __floats2half2_rn(t0, t1);
                *(__half2*)h1 = __floats2half2_rn(t2, t3);
            } else {
                float* o0 = g_Y + (size_t)(e*Tm + row0 + r0)*NTOT + col0;
                float* o1 = g_Y + (size_t)(e*Tm + row0 + r0 + 8)*NTOT + col0;
                *(float2*)(o0 + cc) = make_float2(t0, t1);
                *(float2*)(o1 + cc) = make_float2(t2, t3);
            }
        }
    }
}

// ---------------- combine ----------------
__global__ void combine_kernel(float* __restrict__ out) {
    int idx = blockIdx.x * blockDim.x + threadIdx.x;  // float4 index
    if (idx >= Tm*Dm/4) return;
    int t  = idx / (Dm/4);
    int d4 = idx % (Dm/4);
    float w0 = g_topw[t*2 + 0];
    float w1 = g_topw[t*2 + 1];
    int s0 = g_slot[t*2 + 0];
    int s1 = g_slot[t*2 + 1];
    const float4 y0 = *(const float4*)&g_Y[(size_t)s0*Dm + d4*4];
    const float4 y1 = *(const float4*)&g_Y[(size_t)s1*Dm + d4*4];
    float4 o;
    o.x = w0*y0.x + w1*y1.x;
    o.y = w0*y0.y + w1*y1.y;
    o.z = w0*y0.z + w1*y1.z;
    o.w = w0*y0.w + w1*y1.w;
    *(float4*)&out[(size_t)idx*4] = o;
}

// ---------------- launch ----------------
extern "C" void kernel_launch(void* const* d_in, const int* in_sizes, int n_in,
                              void* d_out, int out_size) {
    const float* x  = (const float*)d_in[0];
    const float* Wr = (const float*)d_in[1];
    const float* W1 = (const float*)d_in[2];
    const float* b1 = (const float*)d_in[3];
    const float* W2 = (const float*)d_in[4];
    const float* b2 = (const float*)d_in[5];
    float* out = (float*)d_out;

    auto k1 = moe_gemm<Dm, Dm, true,  Dm, Fm, true>;   // H = gelu(Xh @ W1h^T + b1)
    auto k2 = moe_gemm<Fm, Fm, false, Fm, Dm, false>;  // Y = H @ W2h^T + b2
    static bool attr_done = false;
    if (!attr_done) {
        cudaFuncSetAttribute(k1, cudaFuncAttributeMaxDynamicSharedMemorySize, SMEM_DYN);
        cudaFuncSetAttribute(k2, cudaFuncAttributeMaxDynamicSharedMemorySize, SMEM_DYN);
        attr_done = true;
    }

    __half *w1h_p, *w2h_p;
    cudaGetSymbolAddress((void**)&w1h_p, g_W1h);
    cudaGetSymbolAddress((void**)&w2h_p, g_W2h);

    zero_counts_kernel<<<1, 32>>>();
    router_kernel<<<(Tm*32 + 255)/256, 256>>>(x, Wr);

    // convert both weight tensors to fp16 (k-permuted) in one launch
    const size_t n4 = (size_t)Em*Fm*Dm/4;          // 8.39M float4 per tensor
    convw_kernel<<<(unsigned)(2*n4/256), 256>>>(W1, W2, w1h_p, w2h_p, n4);

    dim3 g1(Fm/128, Tm/128, Em);   // (32, 32, 8)
    k1<<<g1, 256, SMEM_DYN>>>(w1h_p, b1);

    dim3 g2(Dm/128, Tm/128, Em);   // (8, 32, 8)
    k2<<<g2, 256, SMEM_DYN>>>(w2h_p, b2);

    combine_kernel<<<(Tm*Dm/4 + 255)/256, 256>>>(out);
}

// round 14
// speedup vs baseline: 1.3262x; 1.3262x over previous
#include <cuda_runtime.h>
#include <cuda_fp16.h>
#include <math.h>
#include <stdint.h>

#define Dm 1024
#define Fm 4096
#define Em 8
#define Tm 4096
#define TK (Tm*2)

// ---------------- scratch (static device globals) ----------------
__device__ int    g_count[Em];
__device__ int    g_entries[Em*Tm];      // per-expert list: token index
__device__ int    g_slot[TK];            // token,k -> e*Tm+pos
__device__ float  g_topw[TK];
__device__ __half g_Xh0[(size_t)Tm*Dm];          // fp16 k-permuted, even-row phase
__device__ __half g_Xh1[(size_t)Tm*Dm];          // fp16 k-permuted, odd-row phase (halves swapped)
__device__ __half g_W1h[(size_t)Em*Fm*Dm];       // fp16 k-permuted, parity-swapped by n
__device__ __half g_W2h[(size_t)Em*Dm*Fm];       // fp16 k-permuted, parity-swapped by n
__device__ __half g_H[(size_t)Em*Tm*Fm];         // [e][pos][F] fp16, parity-swapped by pos
__device__ float  g_Y[(size_t)Em*Tm*Dm];         // [e][pos][D] fp32

// k-permutation within each 32-element block: thread qc's fragments for the
// two k16-steps are 16 contiguous bytes: offset = qc*8 + s*4 + v.
__device__ __forceinline__ int kperm32(int kk) {
    int qc = (kk & 7) >> 1;
    int s  = (kk >> 4) & 1;
    int v  = (kk & 1) | ((kk & 8) >> 2);
    return (qc << 3) + (s << 2) + v;
}

// ---------------- PTX helpers (base sm_90 ISA only) ----------------
__device__ __forceinline__ uint32_t s2u(const void* p) {
    uint32_t a;
    asm("{ .reg .u64 t; cvta.to.shared.u64 t, %1; cvt.u32.u64 %0, t; }" : "=r"(a) : "l"(p));
    return a;
}

__device__ __forceinline__ void mma_f16(float* d,
                                        uint32_t a0, uint32_t a1, uint32_t a2, uint32_t a3,
                                        uint32_t b0, uint32_t b1) {
    asm volatile(
        "mma.sync.aligned.m16n8k16.row.col.f32.f16.f16.f32 "
        "{%0,%1,%2,%3}, {%4,%5,%6,%7}, {%8,%9}, {%0,%1,%2,%3};"
        : "+f"(d[0]), "+f"(d[1]), "+f"(d[2]), "+f"(d[3])
        : "r"(a0), "r"(a1), "r"(a2), "r"(a3), "r"(b0), "r"(b1));
}

#define BULK128(dst, src, mbar) \
    asm volatile("cp.async.bulk.shared::cluster.global.mbarrier::complete_tx::bytes [%0], [%1], %2, [%3];" \
        :: "r"(dst), "l"(src), "r"(128), "r"(mbar) : "memory")

#define MBAR_INIT(mbar, cnt) \
    asm volatile("mbarrier.init.shared.b64 [%0], %1;" :: "r"(mbar), "r"((uint32_t)(cnt)) : "memory")
#define MBAR_EXPECT_TX(mbar, bytes) \
    asm volatile("mbarrier.arrive.expect_tx.shared.b64 _, [%0], %1;" :: "r"(mbar), "r"((uint32_t)(bytes)) : "memory")

#define WAIT_PARITY(mbar, ph) do {                                               \
    uint32_t _m = (mbar), _p = (uint32_t)(ph), _d;                               \
    asm volatile(                                                                \
        "{\n\t.reg .pred p;\n\t"                                                 \
        "mbarrier.try_wait.parity.acquire.cta.shared::cta.b64 p, [%1], %2;\n\t"  \
        "selp.b32 %0, 1, 0, p;\n\t}"                                             \
        : "=r"(_d) : "r"(_m), "r"(_p) : "memory");                               \
    if (!_d) {                                                                   \
        asm volatile(                                                            \
            "{\n\t.reg .pred P1;\n\t"                                            \
            "W_%=:\n\t"                                                          \
            "mbarrier.try_wait.parity.acquire.cta.shared::cta.b64 P1, [%0], %1, 0x989680;\n\t" \
            "@P1 bra.uni D_%=;\n\t"                                              \
            "bra.uni W_%=;\n\t"                                                  \
            "D_%=:\n\t}"                                                         \
            :: "r"(_m), "r"(_p) : "memory");                                     \
    }                                                                            \
} while (0)

// ---------------- weight convert (both weights, one launch) ---------------
// fp32 -> fp16, kperm32 within 32-blocks, 64B-half swap iff weight row n odd.
__global__ void convw_kernel(const float* __restrict__ W1, const float* __restrict__ W2,
                             __half* __restrict__ D1, __half* __restrict__ D2,
                             size_t n4) {
    size_t i4 = (size_t)blockIdx.x * blockDim.x + threadIdx.x;
    const float* src;
    __half* dst;
    size_t base;
    int shift;
    if (i4 < n4) { src = W1; dst = D1; base = i4 * 4;        shift = 10; }   // row stride 1024
    else         { src = W2; dst = D2; base = (i4 - n4) * 4; shift = 12; }   // row stride 4096
    float4 v = *(const float4*)(src + base);
    int kk = (int)(base & 31);                  // 4-aligned
    int s  = (kk >> 4) & 1;
    int h  = ((kk & 7) >> 1) * 8 + s * 4 + ((kk & 8) >> 2);
    int rp = (int)((base >> shift) & 1);        // row parity
    size_t out = (base & ~(size_t)63) | ((size_t)((((int)(base >> 5) & 1) ^ rp) << 5));
    *(__half2*)(dst + out + h)     = __floats2half2_rn(v.x, v.y);
    *(__half2*)(dst + out + h + 8) = __floats2half2_rn(v.z, v.w);
}

// ---------------- router ----------------
__global__ void zero_counts_kernel() {
    if (threadIdx.x < Em) g_count[threadIdx.x] = 0;
}

__global__ void router_kernel(const float* __restrict__ x,
                              const float* __restrict__ Wr) {
    int w    = (blockIdx.x * blockDim.x + threadIdx.x) >> 5;
    int lane = threadIdx.x & 31;
    if (w >= Tm) return;
    const float* xr = x + (size_t)w * Dm;
    __half* xo0 = g_Xh0 + (size_t)w * Dm;
    __half* xo1 = g_Xh1 + (size_t)w * Dm;
    float acc[Em];
#pragma unroll
    for (int e = 0; e < Em; e++) acc[e] = 0.f;
    for (int j = lane; j < Dm; j += 32) {
        float xv = xr[j];
        __half hv = __float2half_rn(xv);
        int h   = kperm32(j & 31);
        int b64 = j & ~63;
        int blk = (j >> 5) & 1;
        xo0[b64 + (blk << 5) + h]       = hv;
        xo1[b64 + ((blk ^ 1) << 5) + h] = hv;
#pragma unroll
        for (int e = 0; e < Em; e++) acc[e] = fmaf(xv, Wr[e*Dm + j], acc[e]);
    }
#pragma unroll
    for (int e = 0; e < Em; e++) {
#pragma unroll
        for (int off = 16; off; off >>= 1)
            acc[e] += __shfl_xor_sync(0xffffffffu, acc[e], off);
    }
    if (lane == 0) {
        int e0 = 0; float v0 = acc[0];
#pragma unroll
        for (int e = 1; e < Em; e++) if (acc[e] > v0) { v0 = acc[e]; e0 = e; }
        int e1 = -1; float v1 = -1e30f;
#pragma unroll
        for (int e = 0; e < Em; e++) if (e != e0 && acc[e] > v1) { v1 = acc[e]; e1 = e; }
        float b  = expf(v1 - v0);
        g_topw[w*2 + 0] = 1.f / (1.f + b);
        g_topw[w*2 + 1] = b  / (1.f + b);
        int p0 = atomicAdd(&g_count[e0], 1);
        g_entries[e0*Tm + p0] = w;
        g_slot[w*2 + 0] = e0*Tm + p0;
        int p1 = atomicAdd(&g_count[e1], 1);
        g_entries[e1*Tm + p1] = w;
        g_slot[w*2 + 1] = e1*Tm + p1;
    }
}

// ---------------- fp16 m16n8k16 GEMM, 3-stage, 128B bulks, padding-free ---
// block tile 128(M) x 128(N), K-chunk 64 = one 128B row per thread per chunk.
// Parity half-swap in gmem layout -> conflict-free LDS.128 with zero padding.
// 8 warps @ 64x32. 3 stages x 32KB = 96KB -> 2 CTAs/SM.
#define A_HALF 16384
#define LSTG_BYTES 32768
#define NSTG 3
#define SMEM_DYN (NSTG*LSTG_BYTES)                  // 98304
#define TX_BYTES 32768

template<int KTOT, int ASTRIDE, bool GATHER, int BSTRIDE, int NTOT, bool GELU>
__global__ __launch_bounds__(256, 2)
void moe_gemm(const __half* __restrict__ W,
              const float* __restrict__ bias)
{
    int e    = blockIdx.z;
    int cnt  = g_count[e];
    int row0 = blockIdx.y * 128;
    if (row0 >= cnt) return;
    int col0 = blockIdx.x * 128;

    extern __shared__ __align__(16) char dsm[];
    __shared__ __align__(8) uint64_t sMbar[NSTG];

    int tid  = threadIdx.x;
    int lane = tid & 31;
    int w    = tid >> 5;

    uint32_t sbase = s2u(dsm);
    uint32_t mb[NSTG];
#pragma unroll
    for (int s = 0; s < NSTG; s++) mb[s] = s2u(&sMbar[s]);

    if (tid == 0) {
#pragma unroll
        for (int s = 0; s < NSTG; s++) MBAR_INIT(mb[s], 1);
    }
    __syncthreads();

    // per-thread bulk source row: tid<128 -> A row tid; else B row tid-128
    const __half* src;
    uint32_t dst;
    if (tid < 128) {
        if (GATHER) {
            int i   = row0 + tid;
            int tok = g_entries[e*Tm + ((i < cnt) ? i : 0)];
            // pick the Xh copy matching this smem row's parity
            const __half* xbase = (tid & 1) ? g_Xh1 : g_Xh0;
            src = xbase + (size_t)tok*ASTRIDE;
        } else {
            src = g_H + (size_t)(e*Tm + row0 + tid)*ASTRIDE;   // H parity == tid parity
        }
        dst = sbase + tid*128;
    } else {
        src = W + (size_t)e*Fm*Dm + (size_t)(col0 + tid - 128)*BSTRIDE;
        dst = sbase + A_HALF + (tid - 128)*128;
    }

    constexpr int NCHL = KTOT / 64;

    auto loadChunk = [&](int l, int lstg) {
        if (tid == 0) MBAR_EXPECT_TX(mb[lstg], TX_BYTES);
        BULK128(dst + lstg*LSTG_BYTES, src + (size_t)l*64, mb[lstg]);
    };

    loadChunk(0, 0); loadChunk(1, 1); loadChunk(2, 2);

    float acc[4][4][4];
#pragma unroll
    for (int i = 0; i < 4; i++)
#pragma unroll
        for (int j = 0; j < 4; j++)
#pragma unroll
            for (int q = 0; q < 4; q++) acc[i][j][q] = 0.f;

    int wm = w & 1, wn = w >> 1;    // warp tile rows wm*64..+63, cols wn*32..+31
    int qr = lane >> 2;
    int qc = lane & 3;
    int xa = (qr & 1) << 6;         // per-thread constant un-swap XOR

    int lstg = 0, par = 0;

    for (int l = 0; l < NCHL; l++) {
        WAIT_PARITY(mb[lstg], par);

        const char* As = dsm + lstg*LSTG_BYTES;
        const char* Bs = As + A_HALF;

#pragma unroll
        for (int h = 0; h < 2; h++) {
            int ofs = ((h << 6) ^ xa) + qc*16;
            uint4 Alo[4], Ahi[4], Bv[4];
#pragma unroll
            for (int mt = 0; mt < 4; mt++) {
                int r = wm*64 + mt*16 + qr;
                Alo[mt] = *(const uint4*)(As + r*128 + ofs);
                Ahi[mt] = *(const uint4*)(As + (r+8)*128 + ofs);
            }
#pragma unroll
            for (int nt = 0; nt < 4; nt++) {
                int n = wn*32 + nt*8 + qr;
                Bv[nt] = *(const uint4*)(Bs + n*128 + ofs);
            }
#pragma unroll
            for (int s = 0; s < 2; s++) {
#pragma unroll
                for (int mt = 0; mt < 4; mt++) {
                    const uint32_t* al = (const uint32_t*)&Alo[mt];
                    const uint32_t* ah = (const uint32_t*)&Ahi[mt];
#pragma unroll
                    for (int nt = 0; nt < 4; nt++) {
                        const uint32_t* bb = (const uint32_t*)&Bv[nt];
                        mma_f16(acc[mt][nt],
                                al[2*s], ah[2*s], al[2*s+1], ah[2*s+1],
                                bb[2*s], bb[2*s+1]);
                    }
                }
            }
        }
        __syncthreads();                 // stage consumed by all warps
        if (l + NSTG < NCHL) loadChunk(l + NSTG, lstg);
        lstg++; if (lstg == NSTG) { lstg = 0; par ^= 1; }
    }

    // ---- epilogue ----
    const float* bia = bias + e*NTOT + col0;
    int hpar = qr & 1;                  // H-row parity for both r0 and r0+8
#pragma unroll
    for (int mt = 0; mt < 4; mt++) {
        int r0 = wm*64 + mt*16 + qr;
#pragma unroll
        for (int nt = 0; nt < 4; nt++) {
            int cc = wn*32 + nt*8 + 2*qc;
            float bv0 = bia[cc], bv1 = bia[cc + 1];
            float t0 = acc[mt][nt][0] + bv0;
            float t1 = acc[mt][nt][1] + bv1;
            float t2 = acc[mt][nt][2] + bv0;
            float t3 = acc[mt][nt][3] + bv1;
            if (GELU) {
                t0 = 0.5f*t0*(1.f + erff(t0*0.70710678118654752f));
                t1 = 0.5f*t1*(1.f + erff(t1*0.70710678118654752f));
                t2 = 0.5f*t2*(1.f + erff(t2*0.70710678118654752f));
                t3 = 0.5f*t3*(1.f + erff(t3*0.70710678118654752f));
                int po = (cc & ~63) + ((((cc >> 5) & 1) ^ hpar) << 5) + kperm32(cc & 31);
                __half* h0 = g_H + (size_t)(e*Tm + row0 + r0)*NTOT + col0 + po;
                __half* h1 = g_H + (size_t)(e*Tm + row0 + r0 + 8)*NTOT + col0 + po;
                *(__half2*)h0 = __floats2half2_rn(t0, t1);
                *(__half2*)h1 = __floats2half2_rn(t2, t3);
            } else {
                float* o0 = g_Y + (size_t)(e*Tm + row0 + r0)*NTOT + col0;
                float* o1 = g_Y + (size_t)(e*Tm + row0 + r0 + 8)*NTOT + col0;
                *(float2*)(o0 + cc) = make_float2(t0, t1);
                *(float2*)(o1 + cc) = make_float2(t2, t3);
            }
        }
    }
}

// ---------------- combine ----------------
__global__ void combine_kernel(float* __restrict__ out) {
    int idx = blockIdx.x * blockDim.x + threadIdx.x;  // float4 index
    if (idx >= Tm*Dm/4) return;
    int t  = idx / (Dm/4);
    int d4 = idx % (Dm/4);
    float w0 = g_topw[t*2 + 0];
    float w1 = g_topw[t*2 + 1];
    int s0 = g_slot[t*2 + 0];
    int s1 = g_slot[t*2 + 1];
    const float4 y0 = *(const float4*)&g_Y[(size_t)s0*Dm + d4*4];
    const float4 y1 = *(const float4*)&g_Y[(size_t)s1*Dm + d4*4];
    float4 o;
    o.x = w0*y0.x + w1*y1.x;
    o.y = w0*y0.y + w1*y1.y;
    o.z = w0*y0.z + w1*y1.z;
    o.w = w0*y0.w + w1*y1.w;
    *(float4*)&out[(size_t)idx*4] = o;
}

// ---------------- launch ----------------
extern "C" void kernel_launch(void* const* d_in, const int* in_sizes, int n_in,
                              void* d_out, int out_size) {
    const float* x  = (const float*)d_in[0];
    const float* Wr = (const float*)d_in[1];
    const float* W1 = (const float*)d_in[2];
    const float* b1 = (const float*)d_in[3];
    const float* W2 = (const float*)d_in[4];
    const float* b2 = (const float*)d_in[5];
    float* out = (float*)d_out;

    auto k1 = moe_gemm<Dm, Dm, true,  Dm, Fm, true>;   // H = gelu(Xh @ W1h^T + b1)
    auto k2 = moe_gemm<Fm, Fm, false, Fm, Dm, false>;  // Y = H @ W2h^T + b2
    static bool attr_done = false;
    if (!attr_done) {
        cudaFuncSetAttribute(k1, cudaFuncAttributeMaxDynamicSharedMemorySize, SMEM_DYN);
        cudaFuncSetAttribute(k2, cudaFuncAttributeMaxDynamicSharedMemorySize, SMEM_DYN);
        attr_done = true;
    }

    __half *w1h_p, *w2h_p;
    cudaGetSymbolAddress((void**)&w1h_p, g_W1h);
    cudaGetSymbolAddress((void**)&w2h_p, g_W2h);

    zero_counts_kernel<<<1, 32>>>();
    router_kernel<<<(Tm*32 + 255)/256, 256>>>(x, Wr);

    // convert both weight tensors to fp16 (k-permuted, parity-swapped)
    const size_t n4 = (size_t)Em*Fm*Dm/4;          // 8.39M float4 per tensor
    convw_kernel<<<(unsigned)(2*n4/256), 256>>>(W1, W2, w1h_p, w2h_p, n4);

    dim3 g1(Fm/128, Tm/128, Em);   // (32, 32, 8)
    k1<<<g1, 256, SMEM_DYN>>>(w1h_p, b1);

    dim3 g2(Dm/128, Tm/128, Em);   // (8, 32, 8)
    k2<<<g2, 256, SMEM_DYN>>>(w2h_p, b2);

    combine_kernel<<<(Tm*Dm/4 + 255)/256, 256>>>(out);
}